// round 14
// baseline (speedup 1.0000x reference)
#include <cuda_runtime.h>
#include <cuda_fp16.h>
#include <cstdint>

#define T_TOK 8192
#define DIM   1024
#define FDIM  4096
#define NEXP  8
#define SLOTS (T_TOK*2)

#define ASTRW 36            // gemm13 smem row stride (32 kpairs + 4 pad)
#define T_BYTES (128*ASTRW*4)       // 18432 per tile, K-tile 64
#define ST13 (3*T_BYTES)            // 55296 per stage (A,B1,B3)
#define XSTRW 136           // epilogue exchange stride (floats)

#define A2STRW 68           // gemm2 smem row stride (64 kpairs + 4 pad)
#define T2_BYTES (128*A2STRW*4)     // 34816 per tile, K-tile 128
#define ST2 (2*T2_BYTES)            // 69632 per stage (A,B)

// ---------------- device scratch (no allocs allowed) ----------------
__device__ float    g_psum[NEXP];
__device__ int      g_cnt[NEXP];
__device__ int      g_fill[NEXP];
__device__ int      g_off[NEXP+1];
__device__ int      g_top[T_TOK*2];
__device__ float    g_w[T_TOK*2];
__device__ int      g_tok_slot[T_TOK*2];
__device__ int      g_slot_tok[SLOTS];
__device__ float    g_slot_gate[SLOTS];
__device__ uint32_t g_xi [(size_t)T_TOK*(DIM/2)];        // x:  [tok][kpair]
__device__ uint32_t g_w1i[(size_t)NEXP*FDIM*(DIM/2)];    // W1: [e][n][kpair]
__device__ uint32_t g_w3i[(size_t)NEXP*FDIM*(DIM/2)];
__device__ uint32_t g_w2i[(size_t)NEXP*DIM*(FDIM/2)];    // W2: [e][n][fpair]
__device__ uint32_t g_Hu [(size_t)SLOTS*(FDIM/2)];       // H:  [slot][fpair]
__device__ float    g_Y  [(size_t)SLOTS*DIM];            // per-slot gated outputs

// ---------------- helpers ----------------
__device__ __forceinline__ uint32_t pack_h2(float lo, float hi){
    uint32_t r;
    asm("cvt.rn.f16x2.f32 %0, %1, %2;" : "=r"(r) : "f"(hi), "f"(lo));
    return r;
}
__device__ __forceinline__ uint32_t smem_u32(const void* p){
    uint32_t a;
    asm("{ .reg .u64 t; cvta.to.shared.u64 t, %1; cvt.u32.u64 %0, t; }" : "=r"(a) : "l"(p));
    return a;
}
__device__ __forceinline__ void cp16(uint32_t dst, const void* src){
    asm volatile("cp.async.ca.shared.global [%0], [%1], 16;" :: "r"(dst), "l"(src));
}
__device__ __forceinline__ void cp_commit(){ asm volatile("cp.async.commit_group;"); }
__device__ __forceinline__ void cp_wait1(){ asm volatile("cp.async.wait_group 1;"); }
__device__ __forceinline__ void cp_wait0(){ asm volatile("cp.async.wait_group 0;"); }

__device__ __forceinline__ void ldsm_x4(uint32_t* r, uint32_t addr){
    asm volatile("ldmatrix.sync.aligned.m8n8.x4.shared.b16 {%0,%1,%2,%3}, [%4];"
        : "=r"(r[0]), "=r"(r[1]), "=r"(r[2]), "=r"(r[3]) : "r"(addr));
}

__device__ __forceinline__ void mma16(float* c, const uint32_t* a, const uint32_t* b){
    asm volatile(
        "mma.sync.aligned.m16n8k16.row.col.f32.f16.f16.f32 "
        "{%0,%1,%2,%3},{%4,%5,%6,%7},{%8,%9},{%0,%1,%2,%3};"
        : "+f"(c[0]), "+f"(c[1]), "+f"(c[2]), "+f"(c[3])
        : "r"(a[0]), "r"(a[1]), "r"(a[2]), "r"(a[3]), "r"(b[0]), "r"(b[1]));
}

// ---------------- init ----------------
__global__ void init_kernel(){
    int i = threadIdx.x;
    if (i < NEXP){ g_psum[i] = 0.f; g_cnt[i] = 0; }
}

// W1/W3: [e][d][n] f32 -> [e][n][kpair] f16x2. 64x64 tiles via smem.
__global__ void cvt_w13_kernel(const float* __restrict__ W1, const float* __restrict__ W3){
    const int kp0 = blockIdx.x * 64;
    const int n0  = blockIdx.y * 64;
    const int e   = blockIdx.z;
    const int tid = threadIdx.x;          // 256
    __shared__ uint32_t ts[64][68];

    const float* Ws[2] = { W1, W3 };
    uint32_t* Gs[2];
    Gs[0] = g_w1i; Gs[1] = g_w3i;
#pragma unroll
    for (int w = 0; w < 2; w++){
        const float* W = Ws[w];
#pragma unroll
        for (int rep = 0; rep < 4; rep++){
            int kp = rep*16 + (tid >> 4);
            int nl = (tid & 15) * 4;
            const float* s = W + ((size_t)e*DIM + 2*(kp0 + kp))*FDIM + n0 + nl;
            float4 a0 = *(const float4*)s;
            float4 a1 = *(const float4*)(s + FDIM);
            *(uint4*)&ts[kp][nl] = make_uint4(pack_h2(a0.x,a1.x), pack_h2(a0.y,a1.y),
                                              pack_h2(a0.z,a1.z), pack_h2(a0.w,a1.w));
        }
        __syncthreads();
#pragma unroll
        for (int rep = 0; rep < 4; rep++){
            int n  = tid & 63;
            int kq = rep*16 + (tid >> 6) * 4;
            uint4 v = make_uint4(ts[kq+0][n], ts[kq+1][n], ts[kq+2][n], ts[kq+3][n]);
            *(uint4*)&Gs[w][((size_t)e*FDIM + n0 + n)*(DIM/2) + kp0 + kq] = v;
        }
        __syncthreads();
    }
}

// W2: [e][f][d] f32 -> [e][d][fpair] f16x2
__global__ void cvt_w2_kernel(const float* __restrict__ W2){
    const int kp0 = blockIdx.x * 64;
    const int n0  = blockIdx.y * 64;
    const int e   = blockIdx.z;
    const int tid = threadIdx.x;
    __shared__ uint32_t ts[64][68];

#pragma unroll
    for (int rep = 0; rep < 4; rep++){
        int kp = rep*16 + (tid >> 4);
        int nl = (tid & 15) * 4;
        const float* s = W2 + ((size_t)e*FDIM + 2*(kp0 + kp))*DIM + n0 + nl;
        float4 a0 = *(const float4*)s;
        float4 a1 = *(const float4*)(s + DIM);
        *(uint4*)&ts[kp][nl] = make_uint4(pack_h2(a0.x,a1.x), pack_h2(a0.y,a1.y),
                                          pack_h2(a0.z,a1.z), pack_h2(a0.w,a1.w));
    }
    __syncthreads();
#pragma unroll
    for (int rep = 0; rep < 4; rep++){
        int n  = tid & 63;
        int kq = rep*16 + (tid >> 6) * 4;
        uint4 v = make_uint4(ts[kq+0][n], ts[kq+1][n], ts[kq+2][n], ts[kq+3][n]);
        *(uint4*)&g_w2i[((size_t)e*DIM + n0 + n)*(FDIM/2) + kp0 + kq] = v;
    }
}

// ---------------- router (fused x fp16 conversion) ----------------
__global__ void router_kernel(const float* __restrict__ x,
                              const float* __restrict__ Wg,
                              const float* __restrict__ bg){
    __shared__ float sps[NEXP];
    __shared__ int   scn[NEXP];
    if (threadIdx.x < NEXP){ sps[threadIdx.x] = 0.f; scn[threadIdx.x] = 0; }
    __syncthreads();

    const int lane = threadIdx.x & 31;
    const int t = (blockIdx.x * blockDim.x + threadIdx.x) >> 5;

    float acc[NEXP];
#pragma unroll
    for (int e = 0; e < NEXP; e++) acc[e] = 0.f;

    const float2* xr = (const float2*)(x + (size_t)t * DIM);
    uint32_t* xo = g_xi + (size_t)t * (DIM/2);
    for (int kp = lane; kp < DIM/2; kp += 32){
        float2 v = xr[kp];
        xo[kp] = pack_h2(v.x, v.y);
        const float4* wr0 = (const float4*)(Wg + (2*kp) * NEXP);
        float4 w0 = wr0[0], w1 = wr0[1], w2 = wr0[2], w3 = wr0[3];
        acc[0] = fmaf(v.x, w0.x, fmaf(v.y, w2.x, acc[0]));
        acc[1] = fmaf(v.x, w0.y, fmaf(v.y, w2.y, acc[1]));
        acc[2] = fmaf(v.x, w0.z, fmaf(v.y, w2.z, acc[2]));
        acc[3] = fmaf(v.x, w0.w, fmaf(v.y, w2.w, acc[3]));
        acc[4] = fmaf(v.x, w1.x, fmaf(v.y, w3.x, acc[4]));
        acc[5] = fmaf(v.x, w1.y, fmaf(v.y, w3.y, acc[5]));
        acc[6] = fmaf(v.x, w1.z, fmaf(v.y, w3.z, acc[6]));
        acc[7] = fmaf(v.x, w1.w, fmaf(v.y, w3.w, acc[7]));
    }
#pragma unroll
    for (int e = 0; e < NEXP; e++){
#pragma unroll
        for (int o = 16; o > 0; o >>= 1)
            acc[e] += __shfl_xor_sync(0xffffffffu, acc[e], o);
    }

    if (lane == 0){
        float p[NEXP];
        float mx = -1e30f;
#pragma unroll
        for (int e = 0; e < NEXP; e++){ p[e] = acc[e] + bg[e]; mx = fmaxf(mx, p[e]); }
        float s = 0.f;
#pragma unroll
        for (int e = 0; e < NEXP; e++){ p[e] = __expf(p[e] - mx); s += p[e]; }
        float inv = 1.f / s;
#pragma unroll
        for (int e = 0; e < NEXP; e++) p[e] *= inv;

        int e0 = 0;
#pragma unroll
        for (int e = 1; e < NEXP; e++) if (p[e] > p[e0]) e0 = e;
        int e1 = (e0 == 0) ? 1 : 0;
#pragma unroll
        for (int e = 0; e < NEXP; e++) if (e != e0 && p[e] > p[e1]) e1 = e;

        g_top[2*t]   = e0;  g_top[2*t+1] = e1;
        g_w[2*t]     = p[e0]; g_w[2*t+1]  = p[e1];
#pragma unroll
        for (int e = 0; e < NEXP; e++) atomicAdd(&sps[e], p[e]);
        atomicAdd(&scn[e0], 1);
        atomicAdd(&scn[e1], 1);
    }
    __syncthreads();
    if (threadIdx.x < NEXP){
        atomicAdd(&g_psum[threadIdx.x], sps[threadIdx.x]);
        atomicAdd(&g_cnt[threadIdx.x],  scn[threadIdx.x]);
    }
}

// ---------------- offsets + aux ----------------
__global__ void offsets_aux_kernel(float* __restrict__ out, int out_size){
    if (threadIdx.x == 0 && blockIdx.x == 0){
        int off = 0;
        float aux = 0.f;
        for (int e = 0; e < NEXP; e++){
            g_off[e] = off;
            off += g_cnt[e];
            aux += ((float)g_cnt[e] / (float)(T_TOK*2)) * (g_psum[e] / (float)T_TOK);
            g_fill[e] = 0;
        }
        g_off[NEXP] = off;
        if (out_size > T_TOK*DIM) out[T_TOK*DIM] = aux * (float)NEXP;
    }
}

// ---------------- scatter ----------------
__global__ void scatter_kernel(){
    int t = blockIdx.x * blockDim.x + threadIdx.x;
#pragma unroll
    for (int k = 0; k < 2; k++){
        int e = g_top[2*t+k];
        int pos = atomicAdd(&g_fill[e], 1);
        int slot = g_off[e] + pos;
        g_slot_tok[slot]  = t;
        g_slot_gate[slot] = g_w[2*t+k];
        g_tok_slot[2*t+k] = slot;
    }
}

// ---------------- grouped GEMM 1&3 + SwiGLU (K-tile 64, 3-stage) -----------
__global__ __launch_bounds__(512) void gemm13_kernel(){
    const int e   = blockIdx.z;
    const int off = g_off[e];
    const int cnt = g_off[e+1] - off;
    const int m0  = blockIdx.x * 128;
    if (m0 >= cnt) return;
    const int n0  = blockIdx.y * 128;

    extern __shared__ __align__(16) uint32_t dynu[];
    __shared__ int sTok[128];

    const int tid = threadIdx.x;
    if (tid < 128){
        int m = m0 + tid; if (m >= cnt) m = cnt - 1;
        sTok[tid] = g_slot_tok[off + m];
    }
    __syncthreads();

    const uint32_t smBase = smem_u32(dynu);
    const int row = tid >> 2;
    const int q   = tid & 3;

    const uint32_t* aSrc  = g_xi  + (size_t)sTok[row]*(DIM/2) + q*4;
    const uint32_t* b1Src = g_w1i + ((size_t)e*FDIM + n0 + row)*(DIM/2) + q*4;
    const uint32_t* b3Src = g_w3i + ((size_t)e*FDIM + n0 + row)*(DIM/2) + q*4;
    const uint32_t aDst  = smBase + (uint32_t)(row*ASTRW + q*4)*4u;
    const uint32_t b1Dst = smBase + T_BYTES + (uint32_t)(row*ASTRW + q*4)*4u;
    const uint32_t b3Dst = smBase + 2*T_BYTES + (uint32_t)(row*ASTRW + q*4)*4u;

    auto ISSUE = [&](int kt, int s){
        uint32_t so = (uint32_t)s * ST13;
        const int ko = kt * 32;
        cp16(aDst  + so,      aSrc  + ko);
        cp16(aDst  + so + 64, aSrc  + ko + 16);
        cp16(b1Dst + so,      b1Src + ko);
        cp16(b1Dst + so + 64, b1Src + ko + 16);
        cp16(b3Dst + so,      b3Src + ko);
        cp16(b3Dst + so + 64, b3Src + ko + 16);
        cp_commit();
    };

    float acc[2][8][4];
#pragma unroll
    for (int i = 0; i < 2; i++)
#pragma unroll
        for (int j = 0; j < 8; j++)
#pragma unroll
            for (int k = 0; k < 4; k++) acc[i][j][k] = 0.f;

    const int lane = tid & 31, wid = tid >> 5;
    const int MAT = wid >> 3;
    const int wg  = wid & 7;
    const int wm = (wg & 3) * 32, wn = (wg >> 2) * 64;
    const int g = lane >> 2, tg = lane & 3;
    const int lrow = lane & 15;
    const int lkp4 = (lane >> 4) * 4;
    const int lm = lane >> 3, lr = lane & 7;

    auto COMPUTE = [&](int s){
        const uint32_t abase = smBase + (uint32_t)s * ST13;
        const uint32_t bbase = abase + T_BYTES + (MAT ? T_BYTES : 0);
#pragma unroll
        for (int ks = 0; ks < 4; ks++){
            const int kp0 = ks * 8;
            uint32_t af[2][4];
#pragma unroll
            for (int mi = 0; mi < 2; mi++)
                ldsm_x4(af[mi], abase + (uint32_t)((wm + mi*16 + lrow)*ASTRW + kp0 + lkp4)*4u);
#pragma unroll
            for (int p = 0; p < 4; p++){
                uint32_t bfr[4];
                int bn = wn + p*16 + ((lm >> 1) << 3) + lr;
                ldsm_x4(bfr, bbase + (uint32_t)(bn*ASTRW + kp0 + ((lm & 1) << 2))*4u);
#pragma unroll
                for (int mi = 0; mi < 2; mi++){
                    mma16(acc[mi][2*p],   af[mi], &bfr[0]);
                    mma16(acc[mi][2*p+1], af[mi], &bfr[2]);
                }
            }
        }
    };

    const int NK = DIM / 64;
    ISSUE(0, 0); ISSUE(1, 1);
    int buf = 0;
    for (int kt = 0; kt < NK; kt++){
        if (kt == NK-1) cp_wait0(); else cp_wait1();
        __syncthreads();
        if (kt + 2 < NK){
            int nb = buf + 2; if (nb >= 3) nb -= 3;
            ISSUE(kt + 2, nb);
        }
        COMPUTE(buf);
        if (++buf == 3) buf = 0;
    }

    __syncthreads();
    float* sx = (float*)dynu;
    if (MAT == 1){
#pragma unroll
        for (int mi = 0; mi < 2; mi++)
#pragma unroll
            for (int ni = 0; ni < 8; ni++){
                int c = wn + ni * 8 + tg * 2;
#pragma unroll
                for (int h = 0; h < 2; h++){
                    int r = wm + mi * 16 + g + h * 8;
                    *(float2*)&sx[r*XSTRW + c] =
                        make_float2(acc[mi][ni][h*2], acc[mi][ni][h*2+1]);
                }
            }
    }
    __syncthreads();
    if (MAT == 0){
#pragma unroll
        for (int mi = 0; mi < 2; mi++)
#pragma unroll
            for (int ni = 0; ni < 8; ni++){
                int c = wn + ni * 8 + tg * 2;
#pragma unroll
                for (int h = 0; h < 2; h++){
                    int r = wm + mi * 16 + g + h * 8;
                    int m = m0 + r;
                    if (m < cnt){
                        float2 v3 = *(const float2*)&sx[r*XSTRW + c];
                        float v1a = acc[mi][ni][h*2], v1b = acc[mi][ni][h*2+1];
                        float ox = (v1a / (1.f + __expf(-v1a))) * v3.x;
                        float oy = (v1b / (1.f + __expf(-v1b))) * v3.y;
                        g_Hu[(size_t)(off + m)*(FDIM/2) + ((n0 + c) >> 1)] = pack_h2(ox, oy);
                    }
                }
            }
    }
}

// ---------------- grouped GEMM 2 (H @ W2) + gate (K-tile 128, 2-stage) -----
__global__ __launch_bounds__(512) void gemm2_kernel(){
    const int e   = blockIdx.z;
    const int off = g_off[e];
    const int cnt = g_off[e+1] - off;
    const int m0  = blockIdx.x * 128;
    if (m0 >= cnt) return;
    const int n0  = blockIdx.y * 128;

    extern __shared__ __align__(16) uint32_t dynu[];

    const int tid = threadIdx.x;
    const uint32_t smBase = smem_u32(dynu);
    const int row = tid >> 2;            // 0..127
    const int q   = tid & 3;             // quarter of 64 kpairs

    int mrow = m0 + row; if (mrow >= cnt) mrow = cnt - 1;
    const uint32_t* aSrc = g_Hu  + (size_t)(off + mrow)*(FDIM/2) + q*16;
    const uint32_t* bSrc = g_w2i + ((size_t)e*DIM + n0 + row)*(FDIM/2) + q*16;
    const uint32_t aDst = smBase + (uint32_t)(row*A2STRW + q*16)*4u;
    const uint32_t bDst = smBase + T2_BYTES + (uint32_t)(row*A2STRW + q*16)*4u;

    auto ISSUE = [&](int kt, int s){
        uint32_t so = (uint32_t)s * ST2;
        const int ko = kt * 64;
#pragma unroll
        for (int i = 0; i < 4; i++){
            cp16(aDst + so + i*16, aSrc + ko + i*4);
            cp16(bDst + so + i*16, bSrc + ko + i*4);
        }
        cp_commit();
    };

    float acc[2][4][4];
#pragma unroll
    for (int i = 0; i < 2; i++)
#pragma unroll
        for (int j = 0; j < 4; j++)
#pragma unroll
            for (int k = 0; k < 4; k++) acc[i][j][k] = 0.f;

    const int lane = tid & 31, wid = tid >> 5;
    const int wm = (wid & 3) * 32, wn = (wid >> 2) * 32;
    const int g = lane >> 2, tg = lane & 3;
    const int lrow = lane & 15;
    const int lkp4 = (lane >> 4) * 4;
    const int lm = lane >> 3, lr = lane & 7;

    auto COMPUTE = [&](int s){
        const uint32_t abase = smBase + (uint32_t)s * ST2;
        const uint32_t bbase = abase + T2_BYTES;
#pragma unroll
        for (int ks = 0; ks < 8; ks++){
            const int kp0 = ks * 8;
            uint32_t af[2][4];
#pragma unroll
            for (int mi = 0; mi < 2; mi++)
                ldsm_x4(af[mi], abase + (uint32_t)((wm + mi*16 + lrow)*A2STRW + kp0 + lkp4)*4u);
#pragma unroll
            for (int p = 0; p < 2; p++){
                uint32_t bfr[4];
                int bn = wn + p*16 + ((lm >> 1) << 3) + lr;
                ldsm_x4(bfr, bbase + (uint32_t)(bn*A2STRW + kp0 + ((lm & 1) << 2))*4u);
#pragma unroll
                for (int mi = 0; mi < 2; mi++){
                    mma16(acc[mi][2*p],   af[mi], &bfr[0]);
                    mma16(acc[mi][2*p+1], af[mi], &bfr[2]);
                }
            }
        }
    };

    const int NK = FDIM / 128;                // 32
    ISSUE(0, 0);
    for (int kt = 0; kt < NK; kt++){
        cp_wait0();
        __syncthreads();
        if (kt + 1 < NK) ISSUE(kt + 1, (kt + 1) & 1);
        COMPUTE(kt & 1);
    }

#pragma unroll
    for (int mi = 0; mi < 2; mi++){
#pragma unroll
        for (int h = 0; h < 2; h++){
            int r = wm + mi * 16 + g + h * 8;
            int m = m0 + r;
            if (m < cnt){
                float gate = g_slot_gate[off + m];
#pragma unroll
                for (int ni = 0; ni < 4; ni++){
                    int col = n0 + wn + ni * 8 + tg * 2;
                    float2 o;
                    o.x = acc[mi][ni][h*2]   * gate;
                    o.y = acc[mi][ni][h*2+1] * gate;
                    *(float2*)&g_Y[(size_t)(off + m) * DIM + col] = o;
                }
            }
        }
    }
}

// ---------------- combine two slots per token ----------------
__global__ void combine_kernel(float* __restrict__ out){
    int i = blockIdx.x * blockDim.x + threadIdx.x;
    int t = i >> 8;
    int rem = i & 255;
    int s0 = g_tok_slot[2*t], s1 = g_tok_slot[2*t+1];
    const float4* Y = (const float4*)g_Y;
    float4 a = Y[(size_t)s0 * 256 + rem];
    float4 b = Y[(size_t)s1 * 256 + rem];
    ((float4*)out)[i] = make_float4(a.x + b.x, a.y + b.y, a.z + b.z, a.w + b.w);
}

// ---------------- launch ----------------
extern "C" void kernel_launch(void* const* d_in, const int* in_sizes, int n_in,
                              void* d_out, int out_size){
    const float* x  = (const float*)d_in[0];
    const float* Wg = (const float*)d_in[1];
    const float* bg = (const float*)d_in[2];
    const float* W1 = (const float*)d_in[3];
    const float* W3 = (const float*)d_in[4];
    const float* W2 = (const float*)d_in[5];
    float* out = (float*)d_out;

    const int dyn13 = 3 * ST13;   // 165888 B
    const int dyn2  = 2 * ST2;    // 139264 B
    cudaFuncSetAttribute(gemm13_kernel, cudaFuncAttributeMaxDynamicSharedMemorySize, dyn13);
    cudaFuncSetAttribute(gemm2_kernel,  cudaFuncAttributeMaxDynamicSharedMemorySize, dyn2);

    init_kernel<<<1, 32>>>();
    cvt_w13_kernel<<<dim3((DIM/2)/64, FDIM/64, NEXP), 256>>>(W1, W3);
    cvt_w2_kernel <<<dim3((FDIM/2)/64, DIM/64, NEXP), 256>>>(W2);
    router_kernel<<<T_TOK/8, 256>>>(x, Wg, bg);
    offsets_aux_kernel<<<1, 1>>>(out, out_size);
    scatter_kernel<<<T_TOK/256, 256>>>();
    gemm13_kernel<<<dim3(SLOTS/128, FDIM/128, NEXP), 512, dyn13>>>();
    gemm2_kernel <<<dim3(SLOTS/128, DIM/128,  NEXP), 512, dyn2 >>>();
    combine_kernel<<<(T_TOK*DIM/4)/256, 256>>>(out);
}

// round 15
// speedup vs baseline: 1.0618x; 1.0618x over previous
#include <cuda_runtime.h>
#include <cuda_fp16.h>
#include <cstdint>

#define T_TOK 8192
#define DIM   1024
#define FDIM  4096
#define NEXP  8
#define SLOTS (T_TOK*2)

#define ASTRW 36            // smem row stride in words (32 kpairs + 4 pad) -> conflict-free
#define XSTRW 136           // epilogue exchange stride (floats)
#define T_BYTES (128*ASTRW*4)       // 18432 per tile (A or B), K-tile = 64
#define ST13 (3*T_BYTES)            // 55296 per stage (A,B1,B3)
#define ST2  (2*T_BYTES)            // 36864 per stage (A,B)

// ---------------- device scratch (no allocs allowed) ----------------
__device__ float    g_psum[NEXP];
__device__ int      g_cnt[NEXP];
__device__ int      g_fill[NEXP];
__device__ int      g_off[NEXP+1];
__device__ int      g_top[T_TOK*2];
__device__ float    g_w[T_TOK*2];
__device__ int      g_tok_slot[T_TOK*2];
__device__ int      g_slot_tok[SLOTS];
__device__ float    g_slot_gate[SLOTS];
__device__ uint32_t g_xi [(size_t)T_TOK*(DIM/2)];        // x:  [tok][kpair]
__device__ uint32_t g_w1i[(size_t)NEXP*FDIM*(DIM/2)];    // W1: [e][n][kpair]
__device__ uint32_t g_w3i[(size_t)NEXP*FDIM*(DIM/2)];
__device__ uint32_t g_w2i[(size_t)NEXP*DIM*(FDIM/2)];    // W2: [e][n][fpair]
__device__ uint32_t g_Hu [(size_t)SLOTS*(FDIM/2)];       // H:  [slot][fpair]
__device__ float    g_Y  [(size_t)SLOTS*DIM];            // per-slot gated outputs

// ---------------- helpers ----------------
__device__ __forceinline__ uint32_t pack_h2(float lo, float hi){
    uint32_t r;
    asm("cvt.rn.f16x2.f32 %0, %1, %2;" : "=r"(r) : "f"(hi), "f"(lo));
    return r;
}
__device__ __forceinline__ uint32_t smem_u32(const void* p){
    uint32_t a;
    asm("{ .reg .u64 t; cvta.to.shared.u64 t, %1; cvt.u32.u64 %0, t; }" : "=r"(a) : "l"(p));
    return a;
}
__device__ __forceinline__ void cp16(uint32_t dst, const void* src){
    asm volatile("cp.async.ca.shared.global [%0], [%1], 16;" :: "r"(dst), "l"(src));
}
__device__ __forceinline__ void cp_commit(){ asm volatile("cp.async.commit_group;"); }
__device__ __forceinline__ void cp_wait1(){ asm volatile("cp.async.wait_group 1;"); }
__device__ __forceinline__ void cp_wait0(){ asm volatile("cp.async.wait_group 0;"); }

__device__ __forceinline__ void ldsm_x4(uint32_t* r, uint32_t addr){
    asm volatile("ldmatrix.sync.aligned.m8n8.x4.shared.b16 {%0,%1,%2,%3}, [%4];"
        : "=r"(r[0]), "=r"(r[1]), "=r"(r[2]), "=r"(r[3]) : "r"(addr));
}

__device__ __forceinline__ void mma16(float* c, const uint32_t* a, const uint32_t* b){
    asm volatile(
        "mma.sync.aligned.m16n8k16.row.col.f32.f16.f16.f32 "
        "{%0,%1,%2,%3},{%4,%5,%6,%7},{%8,%9},{%0,%1,%2,%3};"
        : "+f"(c[0]), "+f"(c[1]), "+f"(c[2]), "+f"(c[3])
        : "r"(a[0]), "r"(a[1]), "r"(a[2]), "r"(a[3]), "r"(b[0]), "r"(b[1]));
}

// ---------------- init ----------------
__global__ void init_kernel(){
    int i = threadIdx.x;
    if (i < NEXP){ g_psum[i] = 0.f; g_cnt[i] = 0; }
}

// W1/W3: [e][d][n] f32 -> [e][n][kpair] f16x2. 64x64 tiles; 32B-granular writes.
__global__ void cvt_w13_kernel(const float* __restrict__ W1, const float* __restrict__ W3){
    const int kp0 = blockIdx.x * 64;
    const int n0  = blockIdx.y * 64;
    const int e   = blockIdx.z;
    const int tid = threadIdx.x;          // 256
    __shared__ uint32_t ts[64][68];

    const float* Ws[2] = { W1, W3 };
    uint32_t* Gs[2];
    Gs[0] = g_w1i; Gs[1] = g_w3i;
#pragma unroll
    for (int w = 0; w < 2; w++){
        const float* W = Ws[w];
#pragma unroll
        for (int rep = 0; rep < 4; rep++){
            int kp = rep*16 + (tid >> 4);
            int nl = (tid & 15) * 4;
            const float* s = W + ((size_t)e*DIM + 2*(kp0 + kp))*FDIM + n0 + nl;
            float4 a0 = *(const float4*)s;
            float4 a1 = *(const float4*)(s + FDIM);
            *(uint4*)&ts[kp][nl] = make_uint4(pack_h2(a0.x,a1.x), pack_h2(a0.y,a1.y),
                                              pack_h2(a0.z,a1.z), pack_h2(a0.w,a1.w));
        }
        __syncthreads();
#pragma unroll
        for (int rep = 0; rep < 2; rep++){
            int n  = tid & 63;
            int kq = rep*32 + (tid >> 6) * 8;
            uint32_t* d = &Gs[w][((size_t)e*FDIM + n0 + n)*(DIM/2) + kp0 + kq];
            *(uint4*)(d)     = make_uint4(ts[kq+0][n], ts[kq+1][n], ts[kq+2][n], ts[kq+3][n]);
            *(uint4*)(d + 4) = make_uint4(ts[kq+4][n], ts[kq+5][n], ts[kq+6][n], ts[kq+7][n]);
        }
        __syncthreads();
    }
}

// W2: [e][f][d] f32 -> [e][d][fpair] f16x2; 32B-granular writes.
__global__ void cvt_w2_kernel(const float* __restrict__ W2){
    const int kp0 = blockIdx.x * 64;
    const int n0  = blockIdx.y * 64;
    const int e   = blockIdx.z;
    const int tid = threadIdx.x;
    __shared__ uint32_t ts[64][68];

#pragma unroll
    for (int rep = 0; rep < 4; rep++){
        int kp = rep*16 + (tid >> 4);
        int nl = (tid & 15) * 4;
        const float* s = W2 + ((size_t)e*FDIM + 2*(kp0 + kp))*DIM + n0 + nl;
        float4 a0 = *(const float4*)s;
        float4 a1 = *(const float4*)(s + DIM);
        *(uint4*)&ts[kp][nl] = make_uint4(pack_h2(a0.x,a1.x), pack_h2(a0.y,a1.y),
                                          pack_h2(a0.z,a1.z), pack_h2(a0.w,a1.w));
    }
    __syncthreads();
#pragma unroll
    for (int rep = 0; rep < 2; rep++){
        int n  = tid & 63;
        int kq = rep*32 + (tid >> 6) * 8;
        uint32_t* d = &g_w2i[((size_t)e*DIM + n0 + n)*(FDIM/2) + kp0 + kq];
        *(uint4*)(d)     = make_uint4(ts[kq+0][n], ts[kq+1][n], ts[kq+2][n], ts[kq+3][n]);
        *(uint4*)(d + 4) = make_uint4(ts[kq+4][n], ts[kq+5][n], ts[kq+6][n], ts[kq+7][n]);
    }
}

// ---------------- router (fused x fp16 conversion) ----------------
__global__ void router_kernel(const float* __restrict__ x,
                              const float* __restrict__ Wg,
                              const float* __restrict__ bg){
    __shared__ float sps[NEXP];
    __shared__ int   scn[NEXP];
    if (threadIdx.x < NEXP){ sps[threadIdx.x] = 0.f; scn[threadIdx.x] = 0; }
    __syncthreads();

    const int lane = threadIdx.x & 31;
    const int t = (blockIdx.x * blockDim.x + threadIdx.x) >> 5;

    float acc[NEXP];
#pragma unroll
    for (int e = 0; e < NEXP; e++) acc[e] = 0.f;

    const float2* xr = (const float2*)(x + (size_t)t * DIM);
    uint32_t* xo = g_xi + (size_t)t * (DIM/2);
    for (int kp = lane; kp < DIM/2; kp += 32){
        float2 v = xr[kp];
        xo[kp] = pack_h2(v.x, v.y);
        const float4* wr0 = (const float4*)(Wg + (2*kp) * NEXP);
        float4 w0 = wr0[0], w1 = wr0[1], w2 = wr0[2], w3 = wr0[3];
        acc[0] = fmaf(v.x, w0.x, fmaf(v.y, w2.x, acc[0]));
        acc[1] = fmaf(v.x, w0.y, fmaf(v.y, w2.y, acc[1]));
        acc[2] = fmaf(v.x, w0.z, fmaf(v.y, w2.z, acc[2]));
        acc[3] = fmaf(v.x, w0.w, fmaf(v.y, w2.w, acc[3]));
        acc[4] = fmaf(v.x, w1.x, fmaf(v.y, w3.x, acc[4]));
        acc[5] = fmaf(v.x, w1.y, fmaf(v.y, w3.y, acc[5]));
        acc[6] = fmaf(v.x, w1.z, fmaf(v.y, w3.z, acc[6]));
        acc[7] = fmaf(v.x, w1.w, fmaf(v.y, w3.w, acc[7]));
    }
#pragma unroll
    for (int e = 0; e < NEXP; e++){
#pragma unroll
        for (int o = 16; o > 0; o >>= 1)
            acc[e] += __shfl_xor_sync(0xffffffffu, acc[e], o);
    }

    if (lane == 0){
        float p[NEXP];
        float mx = -1e30f;
#pragma unroll
        for (int e = 0; e < NEXP; e++){ p[e] = acc[e] + bg[e]; mx = fmaxf(mx, p[e]); }
        float s = 0.f;
#pragma unroll
        for (int e = 0; e < NEXP; e++){ p[e] = __expf(p[e] - mx); s += p[e]; }
        float inv = 1.f / s;
#pragma unroll
        for (int e = 0; e < NEXP; e++) p[e] *= inv;

        int e0 = 0;
#pragma unroll
        for (int e = 1; e < NEXP; e++) if (p[e] > p[e0]) e0 = e;
        int e1 = (e0 == 0) ? 1 : 0;
#pragma unroll
        for (int e = 0; e < NEXP; e++) if (e != e0 && p[e] > p[e1]) e1 = e;

        g_top[2*t]   = e0;  g_top[2*t+1] = e1;
        g_w[2*t]     = p[e0]; g_w[2*t+1]  = p[e1];
#pragma unroll
        for (int e = 0; e < NEXP; e++) atomicAdd(&sps[e], p[e]);
        atomicAdd(&scn[e0], 1);
        atomicAdd(&scn[e1], 1);
    }
    __syncthreads();
    if (threadIdx.x < NEXP){
        atomicAdd(&g_psum[threadIdx.x], sps[threadIdx.x]);
        atomicAdd(&g_cnt[threadIdx.x],  scn[threadIdx.x]);
    }
}

// ---------------- offsets + aux ----------------
__global__ void offsets_aux_kernel(float* __restrict__ out, int out_size){
    if (threadIdx.x == 0 && blockIdx.x == 0){
        int off = 0;
        float aux = 0.f;
        for (int e = 0; e < NEXP; e++){
            g_off[e] = off;
            off += g_cnt[e];
            aux += ((float)g_cnt[e] / (float)(T_TOK*2)) * (g_psum[e] / (float)T_TOK);
            g_fill[e] = 0;
        }
        g_off[NEXP] = off;
        if (out_size > T_TOK*DIM) out[T_TOK*DIM] = aux * (float)NEXP;
    }
}

// ---------------- scatter ----------------
__global__ void scatter_kernel(){
    int t = blockIdx.x * blockDim.x + threadIdx.x;
#pragma unroll
    for (int k = 0; k < 2; k++){
        int e = g_top[2*t+k];
        int pos = atomicAdd(&g_fill[e], 1);
        int slot = g_off[e] + pos;
        g_slot_tok[slot]  = t;
        g_slot_gate[slot] = g_w[2*t+k];
        g_tok_slot[2*t+k] = slot;
    }
}

// ---------------- grouped GEMM 1&3 + SwiGLU (K-tile 64, 3-stage) -----------
__global__ __launch_bounds__(512) void gemm13_kernel(){
    const int e   = blockIdx.z;
    const int off = g_off[e];
    const int cnt = g_off[e+1] - off;
    const int m0  = blockIdx.x * 128;
    if (m0 >= cnt) return;
    const int n0  = blockIdx.y * 128;

    extern __shared__ __align__(16) uint32_t dynu[];
    __shared__ int sTok[128];

    const int tid = threadIdx.x;
    if (tid < 128){
        int m = m0 + tid; if (m >= cnt) m = cnt - 1;
        sTok[tid] = g_slot_tok[off + m];
    }
    __syncthreads();

    const uint32_t smBase = smem_u32(dynu);
    const int row = tid >> 2;
    const int q   = tid & 3;

    const uint32_t* aSrc  = g_xi  + (size_t)sTok[row]*(DIM/2) + q*4;
    const uint32_t* b1Src = g_w1i + ((size_t)e*FDIM + n0 + row)*(DIM/2) + q*4;
    const uint32_t* b3Src = g_w3i + ((size_t)e*FDIM + n0 + row)*(DIM/2) + q*4;
    const uint32_t aDst  = smBase + (uint32_t)(row*ASTRW + q*4)*4u;
    const uint32_t b1Dst = smBase + T_BYTES + (uint32_t)(row*ASTRW + q*4)*4u;
    const uint32_t b3Dst = smBase + 2*T_BYTES + (uint32_t)(row*ASTRW + q*4)*4u;

    auto ISSUE = [&](int kt, int s){
        uint32_t so = (uint32_t)s * ST13;
        const int ko = kt * 32;
        cp16(aDst  + so,      aSrc  + ko);
        cp16(aDst  + so + 64, aSrc  + ko + 16);
        cp16(b1Dst + so,      b1Src + ko);
        cp16(b1Dst + so + 64, b1Src + ko + 16);
        cp16(b3Dst + so,      b3Src + ko);
        cp16(b3Dst + so + 64, b3Src + ko + 16);
        cp_commit();
    };

    float acc[2][8][4];
#pragma unroll
    for (int i = 0; i < 2; i++)
#pragma unroll
        for (int j = 0; j < 8; j++)
#pragma unroll
            for (int k = 0; k < 4; k++) acc[i][j][k] = 0.f;

    const int lane = tid & 31, wid = tid >> 5;
    const int MAT = wid >> 3;
    const int wg  = wid & 7;
    const int wm = (wg & 3) * 32, wn = (wg >> 2) * 64;
    const int g = lane >> 2, tg = lane & 3;
    const int lrow = lane & 15;
    const int lkp4 = (lane >> 4) * 4;
    const int lm = lane >> 3, lr = lane & 7;

    auto COMPUTE = [&](int s){
        const uint32_t abase = smBase + (uint32_t)s * ST13;
        const uint32_t bbase = abase + T_BYTES + (MAT ? T_BYTES : 0);
#pragma unroll
        for (int ks = 0; ks < 4; ks++){
            const int kp0 = ks * 8;
            uint32_t af[2][4];
#pragma unroll
            for (int mi = 0; mi < 2; mi++)
                ldsm_x4(af[mi], abase + (uint32_t)((wm + mi*16 + lrow)*ASTRW + kp0 + lkp4)*4u);
#pragma unroll
            for (int p = 0; p < 4; p++){
                uint32_t bfr[4];
                int bn = wn + p*16 + ((lm >> 1) << 3) + lr;
                ldsm_x4(bfr, bbase + (uint32_t)(bn*ASTRW + kp0 + ((lm & 1) << 2))*4u);
#pragma unroll
                for (int mi = 0; mi < 2; mi++){
                    mma16(acc[mi][2*p],   af[mi], &bfr[0]);
                    mma16(acc[mi][2*p+1], af[mi], &bfr[2]);
                }
            }
        }
    };

    const int NK = DIM / 64;                  // 16
    ISSUE(0, 0); ISSUE(1, 1);
    int buf = 0;
    for (int kt = 0; kt < NK; kt++){
        if (kt == NK-1) cp_wait0(); else cp_wait1();
        __syncthreads();
        if (kt + 2 < NK){
            int nb = buf + 2; if (nb >= 3) nb -= 3;
            ISSUE(kt + 2, nb);
        }
        COMPUTE(buf);
        if (++buf == 3) buf = 0;
    }

    __syncthreads();
    float* sx = (float*)dynu;
    if (MAT == 1){
#pragma unroll
        for (int mi = 0; mi < 2; mi++)
#pragma unroll
            for (int ni = 0; ni < 8; ni++){
                int c = wn + ni * 8 + tg * 2;
#pragma unroll
                for (int h = 0; h < 2; h++){
                    int r = wm + mi * 16 + g + h * 8;
                    *(float2*)&sx[r*XSTRW + c] =
                        make_float2(acc[mi][ni][h*2], acc[mi][ni][h*2+1]);
                }
            }
    }
    __syncthreads();
    if (MAT == 0){
#pragma unroll
        for (int mi = 0; mi < 2; mi++)
#pragma unroll
            for (int ni = 0; ni < 8; ni++){
                int c = wn + ni * 8 + tg * 2;
#pragma unroll
                for (int h = 0; h < 2; h++){
                    int r = wm + mi * 16 + g + h * 8;
                    int m = m0 + r;
                    if (m < cnt){
                        float2 v3 = *(const float2*)&sx[r*XSTRW + c];
                        float v1a = acc[mi][ni][h*2], v1b = acc[mi][ni][h*2+1];
                        float ox = (v1a / (1.f + __expf(-v1a))) * v3.x;
                        float oy = (v1b / (1.f + __expf(-v1b))) * v3.y;
                        g_Hu[(size_t)(off + m)*(FDIM/2) + ((n0 + c) >> 1)] = pack_h2(ox, oy);
                    }
                }
            }
    }
}

// ---------------- grouped GEMM 2 (H @ W2) + gate -> g_Y (K-tile 64) --------
__global__ __launch_bounds__(512) void gemm2_kernel(){
    const int e   = blockIdx.z;
    const int off = g_off[e];
    const int cnt = g_off[e+1] - off;
    const int m0  = blockIdx.x * 128;
    if (m0 >= cnt) return;
    const int n0  = blockIdx.y * 128;

    extern __shared__ __align__(16) uint32_t dynu[];

    const int tid = threadIdx.x;
    const uint32_t smBase = smem_u32(dynu);
    const int row = tid >> 2;
    const int q   = tid & 3;

    int mrow = m0 + row; if (mrow >= cnt) mrow = cnt - 1;
    const uint32_t* aSrc = g_Hu  + (size_t)(off + mrow)*(FDIM/2) + q*4;
    const uint32_t* bSrc = g_w2i + ((size_t)e*DIM + n0 + row)*(FDIM/2) + q*4;
    const uint32_t aDst = smBase + (uint32_t)(row*ASTRW + q*4)*4u;
    const uint32_t bDst = smBase + T_BYTES + (uint32_t)(row*ASTRW + q*4)*4u;

    auto ISSUE = [&](int kt, int s){
        uint32_t so = (uint32_t)s * ST2;
        const int ko = kt * 32;
        cp16(aDst + so,      aSrc + ko);
        cp16(aDst + so + 64, aSrc + ko + 16);
        cp16(bDst + so,      bSrc + ko);
        cp16(bDst + so + 64, bSrc + ko + 16);
        cp_commit();
    };

    float acc[2][4][4];
#pragma unroll
    for (int i = 0; i < 2; i++)
#pragma unroll
        for (int j = 0; j < 4; j++)
#pragma unroll
            for (int k = 0; k < 4; k++) acc[i][j][k] = 0.f;

    const int lane = tid & 31, wid = tid >> 5;
    const int wm = (wid & 3) * 32, wn = (wid >> 2) * 32;
    const int g = lane >> 2, tg = lane & 3;
    const int lrow = lane & 15;
    const int lkp4 = (lane >> 4) * 4;
    const int lm = lane >> 3, lr = lane & 7;

    auto COMPUTE = [&](int s){
        const uint32_t abase = smBase + (uint32_t)s * ST2;
        const uint32_t bbase = abase + T_BYTES;
#pragma unroll
        for (int ks = 0; ks < 4; ks++){
            const int kp0 = ks * 8;
            uint32_t af[2][4];
#pragma unroll
            for (int mi = 0; mi < 2; mi++)
                ldsm_x4(af[mi], abase + (uint32_t)((wm + mi*16 + lrow)*ASTRW + kp0 + lkp4)*4u);
#pragma unroll
            for (int p = 0; p < 2; p++){
                uint32_t bfr[4];
                int bn = wn + p*16 + ((lm >> 1) << 3) + lr;
                ldsm_x4(bfr, bbase + (uint32_t)(bn*ASTRW + kp0 + ((lm & 1) << 2))*4u);
#pragma unroll
                for (int mi = 0; mi < 2; mi++){
                    mma16(acc[mi][2*p],   af[mi], &bfr[0]);
                    mma16(acc[mi][2*p+1], af[mi], &bfr[2]);
                }
            }
        }
    };

    const int NK = FDIM / 64;                 // 64
    ISSUE(0, 0); ISSUE(1, 1);
    int buf = 0;
    for (int kt = 0; kt < NK; kt++){
        if (kt == NK-1) cp_wait0(); else cp_wait1();
        __syncthreads();
        if (kt + 2 < NK){
            int nb = buf + 2; if (nb >= 3) nb -= 3;
            ISSUE(kt + 2, nb);
        }
        COMPUTE(buf);
        if (++buf == 3) buf = 0;
    }

#pragma unroll
    for (int mi = 0; mi < 2; mi++){
#pragma unroll
        for (int h = 0; h < 2; h++){
            int r = wm + mi * 16 + g + h * 8;
            int m = m0 + r;
            if (m < cnt){
                float gate = g_slot_gate[off + m];
#pragma unroll
                for (int ni = 0; ni < 4; ni++){
                    int col = n0 + wn + ni * 8 + tg * 2;
                    float2 o;
                    o.x = acc[mi][ni][h*2]   * gate;
                    o.y = acc[mi][ni][h*2+1] * gate;
                    *(float2*)&g_Y[(size_t)(off + m) * DIM + col] = o;
                }
            }
        }
    }
}

// ---------------- combine two slots per token ----------------
__global__ void combine_kernel(float* __restrict__ out){
    int i = blockIdx.x * blockDim.x + threadIdx.x;
    int t = i >> 8;
    int rem = i & 255;
    int s0 = g_tok_slot[2*t], s1 = g_tok_slot[2*t+1];
    const float4* Y = (const float4*)g_Y;
    float4 a = Y[(size_t)s0 * 256 + rem];
    float4 b = Y[(size_t)s1 * 256 + rem];
    ((float4*)out)[i] = make_float4(a.x + b.x, a.y + b.y, a.z + b.z, a.w + b.w);
}

// ---------------- launch ----------------
extern "C" void kernel_launch(void* const* d_in, const int* in_sizes, int n_in,
                              void* d_out, int out_size){
    const float* x  = (const float*)d_in[0];
    const float* Wg = (const float*)d_in[1];
    const float* bg = (const float*)d_in[2];
    const float* W1 = (const float*)d_in[3];
    const float* W3 = (const float*)d_in[4];
    const float* W2 = (const float*)d_in[5];
    float* out = (float*)d_out;

    const int dyn13 = 3 * ST13;   // 165888 B
    const int dyn2  = 3 * ST2;    // 110592 B
    cudaFuncSetAttribute(gemm13_kernel, cudaFuncAttributeMaxDynamicSharedMemorySize, dyn13);
    cudaFuncSetAttribute(gemm2_kernel,  cudaFuncAttributeMaxDynamicSharedMemorySize, dyn2);

    init_kernel<<<1, 32>>>();
    cvt_w13_kernel<<<dim3((DIM/2)/64, FDIM/64, NEXP), 256>>>(W1, W3);
    cvt_w2_kernel <<<dim3((FDIM/2)/64, DIM/64, NEXP), 256>>>(W2);
    router_kernel<<<T_TOK/8, 256>>>(x, Wg, bg);
    offsets_aux_kernel<<<1, 1>>>(out, out_size);
    scatter_kernel<<<T_TOK/256, 256>>>();
    gemm13_kernel<<<dim3(SLOTS/128, FDIM/128, NEXP), 512, dyn13>>>();
    gemm2_kernel <<<dim3(SLOTS/128, DIM/128,  NEXP), 512, dyn2 >>>();
    combine_kernel<<<(T_TOK*DIM/4)/256, 256>>>(out);
}

// round 16
// speedup vs baseline: 1.0709x; 1.0086x over previous
#include <cuda_runtime.h>
#include <cuda_fp16.h>
#include <cstdint>

#define T_TOK 8192
#define DIM   1024
#define FDIM  4096
#define NEXP  8
#define SLOTS (T_TOK*2)

#define ASTRW 36            // smem row stride in words (32 kpairs + 4 pad) -> conflict-free
#define XSTRW 136           // epilogue exchange stride (floats)
#define T_BYTES (128*ASTRW*4)       // 18432 per tile (A or B), K-tile = 64
#define ST13 (3*T_BYTES)            // 55296 per stage (A,B1,B3)
#define ST2  (2*T_BYTES)            // 36864 per stage (A,B)

// ---------------- device scratch (no allocs allowed) ----------------
__device__ float    g_psum[NEXP];
__device__ int      g_cnt[NEXP];
__device__ int      g_fill[NEXP];
__device__ int      g_off[NEXP+1];
__device__ int      g_top[T_TOK*2];
__device__ float    g_w[T_TOK*2];
__device__ int      g_tok_slot[T_TOK*2];
__device__ int      g_slot_tok[SLOTS];
__device__ float    g_slot_gate[SLOTS];
__device__ uint32_t g_xi [(size_t)T_TOK*(DIM/2)];        // x:  [tok][kpair]
__device__ uint32_t g_w1i[(size_t)NEXP*FDIM*(DIM/2)];    // W1: [e][n][kpair]
__device__ uint32_t g_w3i[(size_t)NEXP*FDIM*(DIM/2)];
__device__ uint32_t g_w2i[(size_t)NEXP*DIM*(FDIM/2)];    // W2: [e][n][fpair]
__device__ uint32_t g_Hu [(size_t)SLOTS*(FDIM/2)];       // H:  [slot][fpair]
__device__ float    g_Y  [(size_t)SLOTS*DIM];            // per-slot gated outputs

// ---------------- helpers ----------------
__device__ __forceinline__ uint32_t pack_h2(float lo, float hi){
    uint32_t r;
    asm("cvt.rn.f16x2.f32 %0, %1, %2;" : "=r"(r) : "f"(hi), "f"(lo));
    return r;
}
__device__ __forceinline__ uint32_t smem_u32(const void* p){
    uint32_t a;
    asm("{ .reg .u64 t; cvta.to.shared.u64 t, %1; cvt.u32.u64 %0, t; }" : "=r"(a) : "l"(p));
    return a;
}
__device__ __forceinline__ void cp16(uint32_t dst, const void* src){
    asm volatile("cp.async.ca.shared.global [%0], [%1], 16;" :: "r"(dst), "l"(src));
}
__device__ __forceinline__ void cp_commit(){ asm volatile("cp.async.commit_group;"); }
__device__ __forceinline__ void cp_wait1(){ asm volatile("cp.async.wait_group 1;"); }
__device__ __forceinline__ void cp_wait0(){ asm volatile("cp.async.wait_group 0;"); }

__device__ __forceinline__ void ldsm_x4(uint32_t* r, uint32_t addr){
    asm volatile("ldmatrix.sync.aligned.m8n8.x4.shared.b16 {%0,%1,%2,%3}, [%4];"
        : "=r"(r[0]), "=r"(r[1]), "=r"(r[2]), "=r"(r[3]) : "r"(addr));
}

__device__ __forceinline__ void mma16(float* c, const uint32_t* a, const uint32_t* b){
    asm volatile(
        "mma.sync.aligned.m16n8k16.row.col.f32.f16.f16.f32 "
        "{%0,%1,%2,%3},{%4,%5,%6,%7},{%8,%9},{%0,%1,%2,%3};"
        : "+f"(c[0]), "+f"(c[1]), "+f"(c[2]), "+f"(c[3])
        : "r"(a[0]), "r"(a[1]), "r"(a[2]), "r"(a[3]), "r"(b[0]), "r"(b[1]));
}

// ---------------- init ----------------
__global__ void init_kernel(){
    int i = threadIdx.x;
    if (i < NEXP){ g_psum[i] = 0.f; g_cnt[i] = 0; }
}

// W1/W3: [e][d][n] f32 -> [e][n][kpair] f16x2. 64x64 tiles; 32B-granular writes.
__global__ void cvt_w13_kernel(const float* __restrict__ W1, const float* __restrict__ W3){
    const int kp0 = blockIdx.x * 64;
    const int n0  = blockIdx.y * 64;
    const int e   = blockIdx.z;
    const int tid = threadIdx.x;          // 256
    __shared__ uint32_t ts[64][68];

    const float* Ws[2] = { W1, W3 };
    uint32_t* Gs[2];
    Gs[0] = g_w1i; Gs[1] = g_w3i;
#pragma unroll
    for (int w = 0; w < 2; w++){
        const float* W = Ws[w];
#pragma unroll
        for (int rep = 0; rep < 4; rep++){
            int kp = rep*16 + (tid >> 4);
            int nl = (tid & 15) * 4;
            const float* s = W + ((size_t)e*DIM + 2*(kp0 + kp))*FDIM + n0 + nl;
            float4 a0 = *(const float4*)s;
            float4 a1 = *(const float4*)(s + FDIM);
            *(uint4*)&ts[kp][nl] = make_uint4(pack_h2(a0.x,a1.x), pack_h2(a0.y,a1.y),
                                              pack_h2(a0.z,a1.z), pack_h2(a0.w,a1.w));
        }
        __syncthreads();
#pragma unroll
        for (int rep = 0; rep < 2; rep++){
            int n  = tid & 63;
            int kq = rep*32 + (tid >> 6) * 8;
            uint32_t* d = &Gs[w][((size_t)e*FDIM + n0 + n)*(DIM/2) + kp0 + kq];
            *(uint4*)(d)     = make_uint4(ts[kq+0][n], ts[kq+1][n], ts[kq+2][n], ts[kq+3][n]);
            *(uint4*)(d + 4) = make_uint4(ts[kq+4][n], ts[kq+5][n], ts[kq+6][n], ts[kq+7][n]);
        }
        __syncthreads();
    }
}

// W2: [e][f][d] f32 -> [e][d][fpair] f16x2; 32B-granular writes.
__global__ void cvt_w2_kernel(const float* __restrict__ W2){
    const int kp0 = blockIdx.x * 64;
    const int n0  = blockIdx.y * 64;
    const int e   = blockIdx.z;
    const int tid = threadIdx.x;
    __shared__ uint32_t ts[64][68];

#pragma unroll
    for (int rep = 0; rep < 4; rep++){
        int kp = rep*16 + (tid >> 4);
        int nl = (tid & 15) * 4;
        const float* s = W2 + ((size_t)e*FDIM + 2*(kp0 + kp))*DIM + n0 + nl;
        float4 a0 = *(const float4*)s;
        float4 a1 = *(const float4*)(s + DIM);
        *(uint4*)&ts[kp][nl] = make_uint4(pack_h2(a0.x,a1.x), pack_h2(a0.y,a1.y),
                                          pack_h2(a0.z,a1.z), pack_h2(a0.w,a1.w));
    }
    __syncthreads();
#pragma unroll
    for (int rep = 0; rep < 2; rep++){
        int n  = tid & 63;
        int kq = rep*32 + (tid >> 6) * 8;
        uint32_t* d = &g_w2i[((size_t)e*DIM + n0 + n)*(FDIM/2) + kp0 + kq];
        *(uint4*)(d)     = make_uint4(ts[kq+0][n], ts[kq+1][n], ts[kq+2][n], ts[kq+3][n]);
        *(uint4*)(d + 4) = make_uint4(ts[kq+4][n], ts[kq+5][n], ts[kq+6][n], ts[kq+7][n]);
    }
}

// ---------------- router (fused x fp16 conversion) ----------------
__global__ void router_kernel(const float* __restrict__ x,
                              const float* __restrict__ Wg,
                              const float* __restrict__ bg){
    __shared__ float sps[NEXP];
    __shared__ int   scn[NEXP];
    if (threadIdx.x < NEXP){ sps[threadIdx.x] = 0.f; scn[threadIdx.x] = 0; }
    __syncthreads();

    const int lane = threadIdx.x & 31;
    const int t = (blockIdx.x * blockDim.x + threadIdx.x) >> 5;

    float acc[NEXP];
#pragma unroll
    for (int e = 0; e < NEXP; e++) acc[e] = 0.f;

    const float2* xr = (const float2*)(x + (size_t)t * DIM);
    uint32_t* xo = g_xi + (size_t)t * (DIM/2);
    for (int kp = lane; kp < DIM/2; kp += 32){
        float2 v = xr[kp];
        xo[kp] = pack_h2(v.x, v.y);
        const float4* wr0 = (const float4*)(Wg + (2*kp) * NEXP);
        float4 w0 = wr0[0], w1 = wr0[1], w2 = wr0[2], w3 = wr0[3];
        acc[0] = fmaf(v.x, w0.x, fmaf(v.y, w2.x, acc[0]));
        acc[1] = fmaf(v.x, w0.y, fmaf(v.y, w2.y, acc[1]));
        acc[2] = fmaf(v.x, w0.z, fmaf(v.y, w2.z, acc[2]));
        acc[3] = fmaf(v.x, w0.w, fmaf(v.y, w2.w, acc[3]));
        acc[4] = fmaf(v.x, w1.x, fmaf(v.y, w3.x, acc[4]));
        acc[5] = fmaf(v.x, w1.y, fmaf(v.y, w3.y, acc[5]));
        acc[6] = fmaf(v.x, w1.z, fmaf(v.y, w3.z, acc[6]));
        acc[7] = fmaf(v.x, w1.w, fmaf(v.y, w3.w, acc[7]));
    }
#pragma unroll
    for (int e = 0; e < NEXP; e++){
#pragma unroll
        for (int o = 16; o > 0; o >>= 1)
            acc[e] += __shfl_xor_sync(0xffffffffu, acc[e], o);
    }

    if (lane == 0){
        float p[NEXP];
        float mx = -1e30f;
#pragma unroll
        for (int e = 0; e < NEXP; e++){ p[e] = acc[e] + bg[e]; mx = fmaxf(mx, p[e]); }
        float s = 0.f;
#pragma unroll
        for (int e = 0; e < NEXP; e++){ p[e] = __expf(p[e] - mx); s += p[e]; }
        float inv = 1.f / s;
#pragma unroll
        for (int e = 0; e < NEXP; e++) p[e] *= inv;

        int e0 = 0;
#pragma unroll
        for (int e = 1; e < NEXP; e++) if (p[e] > p[e0]) e0 = e;
        int e1 = (e0 == 0) ? 1 : 0;
#pragma unroll
        for (int e = 0; e < NEXP; e++) if (e != e0 && p[e] > p[e1]) e1 = e;

        g_top[2*t]   = e0;  g_top[2*t+1] = e1;
        g_w[2*t]     = p[e0]; g_w[2*t+1]  = p[e1];
#pragma unroll
        for (int e = 0; e < NEXP; e++) atomicAdd(&sps[e], p[e]);
        atomicAdd(&scn[e0], 1);
        atomicAdd(&scn[e1], 1);
    }
    __syncthreads();
    if (threadIdx.x < NEXP){
        atomicAdd(&g_psum[threadIdx.x], sps[threadIdx.x]);
        atomicAdd(&g_cnt[threadIdx.x],  scn[threadIdx.x]);
    }
}

// ---------------- offsets + aux ----------------
__global__ void offsets_aux_kernel(float* __restrict__ out, int out_size){
    if (threadIdx.x == 0 && blockIdx.x == 0){
        int off = 0;
        float aux = 0.f;
        for (int e = 0; e < NEXP; e++){
            g_off[e] = off;
            off += g_cnt[e];
            aux += ((float)g_cnt[e] / (float)(T_TOK*2)) * (g_psum[e] / (float)T_TOK);
            g_fill[e] = 0;
        }
        g_off[NEXP] = off;
        if (out_size > T_TOK*DIM) out[T_TOK*DIM] = aux * (float)NEXP;
    }
}

// ---------------- scatter ----------------
__global__ void scatter_kernel(){
    int t = blockIdx.x * blockDim.x + threadIdx.x;
#pragma unroll
    for (int k = 0; k < 2; k++){
        int e = g_top[2*t+k];
        int pos = atomicAdd(&g_fill[e], 1);
        int slot = g_off[e] + pos;
        g_slot_tok[slot]  = t;
        g_slot_gate[slot] = g_w[2*t+k];
        g_tok_slot[2*t+k] = slot;
    }
}

// ---------------- grouped GEMM 1&3 + SwiGLU (K-tile 64, 3-stage) -----------
__global__ __launch_bounds__(512) void gemm13_kernel(){
    const int e   = blockIdx.z;
    const int off = g_off[e];
    const int cnt = g_off[e+1] - off;
    const int m0  = blockIdx.x * 128;
    if (m0 >= cnt) return;
    const int n0  = blockIdx.y * 128;

    extern __shared__ __align__(16) uint32_t dynu[];
    __shared__ int sTok[128];

    const int tid = threadIdx.x;
    if (tid < 128){
        int m = m0 + tid; if (m >= cnt) m = cnt - 1;
        sTok[tid] = g_slot_tok[off + m];
    }
    __syncthreads();

    const uint32_t smBase = smem_u32(dynu);
    const int row = tid >> 2;
    const int q   = tid & 3;

    const uint32_t* aSrc  = g_xi  + (size_t)sTok[row]*(DIM/2) + q*4;
    const uint32_t* b1Src = g_w1i + ((size_t)e*FDIM + n0 + row)*(DIM/2) + q*4;
    const uint32_t* b3Src = g_w3i + ((size_t)e*FDIM + n0 + row)*(DIM/2) + q*4;
    const uint32_t aDst  = smBase + (uint32_t)(row*ASTRW + q*4)*4u;
    const uint32_t b1Dst = smBase + T_BYTES + (uint32_t)(row*ASTRW + q*4)*4u;
    const uint32_t b3Dst = smBase + 2*T_BYTES + (uint32_t)(row*ASTRW + q*4)*4u;

    auto ISSUE = [&](int kt, int s){
        uint32_t so = (uint32_t)s * ST13;
        const int ko = kt * 32;
        cp16(aDst  + so,      aSrc  + ko);
        cp16(aDst  + so + 64, aSrc  + ko + 16);
        cp16(b1Dst + so,      b1Src + ko);
        cp16(b1Dst + so + 64, b1Src + ko + 16);
        cp16(b3Dst + so,      b3Src + ko);
        cp16(b3Dst + so + 64, b3Src + ko + 16);
        cp_commit();
    };

    float acc[2][8][4];
#pragma unroll
    for (int i = 0; i < 2; i++)
#pragma unroll
        for (int j = 0; j < 8; j++)
#pragma unroll
            for (int k = 0; k < 4; k++) acc[i][j][k] = 0.f;

    const int lane = tid & 31, wid = tid >> 5;
    const int MAT = wid >> 3;
    const int wg  = wid & 7;
    const int wm = (wg & 3) * 32, wn = (wg >> 2) * 64;
    const int g = lane >> 2, tg = lane & 3;
    const int lrow = lane & 15;
    const int lkp4 = (lane >> 4) * 4;
    const int lm = lane >> 3, lr = lane & 7;

    auto COMPUTE = [&](int s){
        const uint32_t abase = smBase + (uint32_t)s * ST13;
        const uint32_t bbase = abase + T_BYTES + (MAT ? T_BYTES : 0);
#pragma unroll
        for (int ks = 0; ks < 4; ks++){
            const int kp0 = ks * 8;
            uint32_t af[2][4];
#pragma unroll
            for (int mi = 0; mi < 2; mi++)
                ldsm_x4(af[mi], abase + (uint32_t)((wm + mi*16 + lrow)*ASTRW + kp0 + lkp4)*4u);
#pragma unroll
            for (int p = 0; p < 4; p++){
                uint32_t bfr[4];
                int bn = wn + p*16 + ((lm >> 1) << 3) + lr;
                ldsm_x4(bfr, bbase + (uint32_t)(bn*ASTRW + kp0 + ((lm & 1) << 2))*4u);
#pragma unroll
                for (int mi = 0; mi < 2; mi++){
                    mma16(acc[mi][2*p],   af[mi], &bfr[0]);
                    mma16(acc[mi][2*p+1], af[mi], &bfr[2]);
                }
            }
        }
    };

    const int NK = DIM / 64;                  // 16
    ISSUE(0, 0); ISSUE(1, 1);
    int buf = 0;
    for (int kt = 0; kt < NK; kt++){
        if (kt == NK-1) cp_wait0(); else cp_wait1();
        __syncthreads();
        if (kt + 2 < NK){
            int nb = buf + 2; if (nb >= 3) nb -= 3;
            ISSUE(kt + 2, nb);
        }
        COMPUTE(buf);
        if (++buf == 3) buf = 0;
    }

    __syncthreads();
    float* sx = (float*)dynu;
    if (MAT == 1){
#pragma unroll
        for (int mi = 0; mi < 2; mi++)
#pragma unroll
            for (int ni = 0; ni < 8; ni++){
                int c = wn + ni * 8 + tg * 2;
#pragma unroll
                for (int h = 0; h < 2; h++){
                    int r = wm + mi * 16 + g + h * 8;
                    *(float2*)&sx[r*XSTRW + c] =
                        make_float2(acc[mi][ni][h*2], acc[mi][ni][h*2+1]);
                }
            }
    }
    __syncthreads();
    if (MAT == 0){
#pragma unroll
        for (int mi = 0; mi < 2; mi++)
#pragma unroll
            for (int ni = 0; ni < 8; ni++){
                int c = wn + ni * 8 + tg * 2;
#pragma unroll
                for (int h = 0; h < 2; h++){
                    int r = wm + mi * 16 + g + h * 8;
                    int m = m0 + r;
                    if (m < cnt){
                        float2 v3 = *(const float2*)&sx[r*XSTRW + c];
                        float v1a = acc[mi][ni][h*2], v1b = acc[mi][ni][h*2+1];
                        float ox = (v1a / (1.f + __expf(-v1a))) * v3.x;
                        float oy = (v1b / (1.f + __expf(-v1b))) * v3.y;
                        g_Hu[(size_t)(off + m)*(FDIM/2) + ((n0 + c) >> 1)] = pack_h2(ox, oy);
                    }
                }
            }
    }
}

// ---------------- grouped GEMM 2 (H @ W2) + gate -> g_Y (K-tile 64) --------
__global__ __launch_bounds__(512) void gemm2_kernel(){
    const int e   = blockIdx.z;
    const int off = g_off[e];
    const int cnt = g_off[e+1] - off;
    const int m0  = blockIdx.x * 128;
    if (m0 >= cnt) return;
    const int n0  = blockIdx.y * 128;

    extern __shared__ __align__(16) uint32_t dynu[];

    const int tid = threadIdx.x;
    const uint32_t smBase = smem_u32(dynu);
    const int row = tid >> 2;
    const int q   = tid & 3;

    int mrow = m0 + row; if (mrow >= cnt) mrow = cnt - 1;
    const uint32_t* aSrc = g_Hu  + (size_t)(off + mrow)*(FDIM/2) + q*4;
    const uint32_t* bSrc = g_w2i + ((size_t)e*DIM + n0 + row)*(FDIM/2) + q*4;
    const uint32_t aDst = smBase + (uint32_t)(row*ASTRW + q*4)*4u;
    const uint32_t bDst = smBase + T_BYTES + (uint32_t)(row*ASTRW + q*4)*4u;

    auto ISSUE = [&](int kt, int s){
        uint32_t so = (uint32_t)s * ST2;
        const int ko = kt * 32;
        cp16(aDst + so,      aSrc + ko);
        cp16(aDst + so + 64, aSrc + ko + 16);
        cp16(bDst + so,      bSrc + ko);
        cp16(bDst + so + 64, bSrc + ko + 16);
        cp_commit();
    };

    float acc[2][4][4];
#pragma unroll
    for (int i = 0; i < 2; i++)
#pragma unroll
        for (int j = 0; j < 4; j++)
#pragma unroll
            for (int k = 0; k < 4; k++) acc[i][j][k] = 0.f;

    const int lane = tid & 31, wid = tid >> 5;
    const int wm = (wid & 3) * 32, wn = (wid >> 2) * 32;
    const int g = lane >> 2, tg = lane & 3;
    const int lrow = lane & 15;
    const int lkp4 = (lane >> 4) * 4;
    const int lm = lane >> 3, lr = lane & 7;

    auto COMPUTE = [&](int s){
        const uint32_t abase = smBase + (uint32_t)s * ST2;
        const uint32_t bbase = abase + T_BYTES;
#pragma unroll
        for (int ks = 0; ks < 4; ks++){
            const int kp0 = ks * 8;
            uint32_t af[2][4];
#pragma unroll
            for (int mi = 0; mi < 2; mi++)
                ldsm_x4(af[mi], abase + (uint32_t)((wm + mi*16 + lrow)*ASTRW + kp0 + lkp4)*4u);
#pragma unroll
            for (int p = 0; p < 2; p++){
                uint32_t bfr[4];
                int bn = wn + p*16 + ((lm >> 1) << 3) + lr;
                ldsm_x4(bfr, bbase + (uint32_t)(bn*ASTRW + kp0 + ((lm & 1) << 2))*4u);
#pragma unroll
                for (int mi = 0; mi < 2; mi++){
                    mma16(acc[mi][2*p],   af[mi], &bfr[0]);
                    mma16(acc[mi][2*p+1], af[mi], &bfr[2]);
                }
            }
        }
    };

    const int NK = FDIM / 64;                 // 64
    ISSUE(0, 0); ISSUE(1, 1);
    int buf = 0;
    for (int kt = 0; kt < NK; kt++){
        if (kt == NK-1) cp_wait0(); else cp_wait1();
        __syncthreads();
        if (kt + 2 < NK){
            int nb = buf + 2; if (nb >= 3) nb -= 3;
            ISSUE(kt + 2, nb);
        }
        COMPUTE(buf);
        if (++buf == 3) buf = 0;
    }

#pragma unroll
    for (int mi = 0; mi < 2; mi++){
#pragma unroll
        for (int h = 0; h < 2; h++){
            int r = wm + mi * 16 + g + h * 8;
            int m = m0 + r;
            if (m < cnt){
                float gate = g_slot_gate[off + m];
#pragma unroll
                for (int ni = 0; ni < 4; ni++){
                    int col = n0 + wn + ni * 8 + tg * 2;
                    float2 o;
                    o.x = acc[mi][ni][h*2]   * gate;
                    o.y = acc[mi][ni][h*2+1] * gate;
                    *(float2*)&g_Y[(size_t)(off + m) * DIM + col] = o;
                }
            }
        }
    }
}

// ---------------- combine two slots per token ----------------
__global__ void combine_kernel(float* __restrict__ out){
    int i = blockIdx.x * blockDim.x + threadIdx.x;
    int t = i >> 8;
    int rem = i & 255;
    int s0 = g_tok_slot[2*t], s1 = g_tok_slot[2*t+1];
    const float4* Y = (const float4*)g_Y;
    float4 a = Y[(size_t)s0 * 256 + rem];
    float4 b = Y[(size_t)s1 * 256 + rem];
    ((float4*)out)[i] = make_float4(a.x + b.x, a.y + b.y, a.z + b.z, a.w + b.w);
}

// ---------------- launch (two-stream fork: cvt path || router path) --------
extern "C" void kernel_launch(void* const* d_in, const int* in_sizes, int n_in,
                              void* d_out, int out_size){
    const float* x  = (const float*)d_in[0];
    const float* Wg = (const float*)d_in[1];
    const float* bg = (const float*)d_in[2];
    const float* W1 = (const float*)d_in[3];
    const float* W3 = (const float*)d_in[4];
    const float* W2 = (const float*)d_in[5];
    float* out = (float*)d_out;

    // One-time resources (created on the first, non-captured correctness call;
    // reused identically on every call -> deterministic, graph-fork capturable).
    static cudaStream_t s1 = nullptr;
    static cudaEvent_t evRoot = nullptr, ev13 = nullptr, ev2 = nullptr;
    if (!s1){
        cudaStreamCreateWithFlags(&s1, cudaStreamNonBlocking);
        cudaEventCreateWithFlags(&evRoot, cudaEventDisableTiming);
        cudaEventCreateWithFlags(&ev13,   cudaEventDisableTiming);
        cudaEventCreateWithFlags(&ev2,    cudaEventDisableTiming);
    }

    const int dyn13 = 3 * ST13;   // 165888 B
    const int dyn2  = 3 * ST2;    // 110592 B
    cudaFuncSetAttribute(gemm13_kernel, cudaFuncAttributeMaxDynamicSharedMemorySize, dyn13);
    cudaFuncSetAttribute(gemm2_kernel,  cudaFuncAttributeMaxDynamicSharedMemorySize, dyn2);

    init_kernel<<<1, 32>>>();
    cudaEventRecord(evRoot, 0);
    cudaStreamWaitEvent(s1, evRoot, 0);

    // Stream s1: weight conversion path
    cvt_w13_kernel<<<dim3((DIM/2)/64, FDIM/64, NEXP), 256, 0, s1>>>(W1, W3);
    cudaEventRecord(ev13, s1);
    cvt_w2_kernel <<<dim3((FDIM/2)/64, DIM/64, NEXP), 256, 0, s1>>>(W2);
    cudaEventRecord(ev2, s1);

    // Main stream: routing path (independent of weight conversion)
    router_kernel<<<T_TOK/8, 256>>>(x, Wg, bg);
    offsets_aux_kernel<<<1, 1>>>(out, out_size);
    scatter_kernel<<<T_TOK/256, 256>>>();

    // gemm13 needs W1/W3 converted + routing done
    cudaStreamWaitEvent(0, ev13, 0);
    gemm13_kernel<<<dim3(SLOTS/128, FDIM/128, NEXP), 512, dyn13>>>();
    // gemm2 additionally needs W2 converted (cvt_w2 overlapped with gemm13)
    cudaStreamWaitEvent(0, ev2, 0);
    gemm2_kernel <<<dim3(SLOTS/128, DIM/128,  NEXP), 512, dyn2 >>>();
    combine_kernel<<<(T_TOK*DIM/4)/256, 256>>>(out);
}